// round 3
// baseline (speedup 1.0000x reference)
#include <cuda_runtime.h>
#include <cmath>

#define NN     100000
#define EE     3200000
#define ETOT   (EE + NN)
#define FIN    512
#define H1D    64      // heads*hid layer1
#define HEADS  8
#define NCLS   16

// ---------------- scratch (device globals; no allocation) ----------------
__device__ __align__(16) static int   g_src[ETOT];
__device__ __align__(16) static int   g_dst[ETOT];
__device__ __align__(16) static float g_h1[(size_t)NN * H1D];
__device__ __align__(16) static float g_as1[NN * HEADS];
__device__ __align__(16) static float g_ad1[NN * HEADS];
__device__ __align__(16) static float g_den1[NN * HEADS];
__device__ __align__(16) static float g_acc1[(size_t)NN * H1D];
__device__ __align__(16) static float g_h2[(size_t)NN * NCLS];
__device__ __align__(16) static float g_as2[NN];
__device__ __align__(16) static float g_ad2[NN];
__device__ __align__(16) static float g_den2[NN];
__device__ static int g_is64;

__device__ __forceinline__ float lrelu(float v) { return v > 0.0f ? v : 0.2f * v; }

// ---------------- detect edge_index dtype (int64 vs int32) ----------------
// int64 values < 2^31 have zero high words at every odd int32 position.
__global__ void k_detect(const int* __restrict__ ei) {
    __shared__ int s;
    if (threadIdx.x == 0) s = 1;
    __syncthreads();
    int bad = 0;
    for (int i = threadIdx.x; i < 1024; i += blockDim.x)
        if (ei[2 * i + 1] != 0) bad = 1;
    if (bad) atomicExch(&s, 0);
    __syncthreads();
    if (threadIdx.x == 0) g_is64 = s;
}

// ---------------- edge materialization (-> int32, add self loops) ----------
__global__ void k_edges(const int* __restrict__ ei, int E, int N) {
    int t = blockIdx.x * blockDim.x + threadIdx.x;
    int tot = E + N;
    if (t >= tot) return;
    if (t < E) {
        if (g_is64) {
            const long long* e64 = (const long long*)ei;
            g_src[t] = (int)e64[t];
            g_dst[t] = (int)e64[(size_t)E + t];
        } else {
            g_src[t] = ei[t];
            g_dst[t] = ei[(size_t)E + t];
        }
    } else {
        g_src[t] = t - E;
        g_dst[t] = t - E;
    }
}

// ---------------- init: zero accumulators, seed output with bias ----------
__global__ void k_init(float* __restrict__ out, const float* __restrict__ b2, int N) {
    int t = blockIdx.x * blockDim.x + threadIdx.x;
    if (t < N * H1D)   g_acc1[t] = 0.0f;
    if (t < N * HEADS) g_den1[t] = 0.0f;
    if (t < N)         g_den2[t] = 0.0f;
    if (t < N * NCLS)  out[t] = b2[t & (NCLS - 1)];
}

// ---------------- GEMM1: g_h1 = x @ W1   [M,512]x[512,64] ----------------
#define GM_BM 128
#define GM_BN 64
#define GM_BK 16
__global__ __launch_bounds__(256) void k_gemm1(const float* __restrict__ X,
                                               const float* __restrict__ W, int M) {
    __shared__ float xs[GM_BK][GM_BM];
    __shared__ float ws[GM_BK][GM_BN];
    const int tid = threadIdx.x;
    const int tx = tid & 15;   // col group (4 cols)
    const int ty = tid >> 4;   // row group (8 rows)
    const int row0 = blockIdx.x * GM_BM;

    float acc[8][4];
#pragma unroll
    for (int i = 0; i < 8; i++)
#pragma unroll
        for (int j = 0; j < 4; j++) acc[i][j] = 0.0f;

    for (int k0 = 0; k0 < FIN; k0 += GM_BK) {
        // load X tile: 128 rows x 16 cols = 512 float4 slots, 2 per thread
#pragma unroll
        for (int i = 0; i < 2; i++) {
            int s = tid + i * 256;
            int r = s >> 2;
            int c4 = s & 3;
            float4 v = make_float4(0.f, 0.f, 0.f, 0.f);
            int gr = row0 + r;
            if (gr < M)
                v = *(const float4*)(X + (size_t)gr * FIN + k0 + c4 * 4);
            xs[c4 * 4 + 0][r] = v.x;
            xs[c4 * 4 + 1][r] = v.y;
            xs[c4 * 4 + 2][r] = v.z;
            xs[c4 * 4 + 3][r] = v.w;
        }
        // load W tile: 16 x 64 = 256 float4 slots, 1 per thread
        {
            int r = tid >> 4;
            int c4 = tid & 15;
            float4 v = *(const float4*)(W + (size_t)(k0 + r) * GM_BN + c4 * 4);
            *(float4*)&ws[r][c4 * 4] = v;
        }
        __syncthreads();
#pragma unroll
        for (int kk = 0; kk < GM_BK; kk++) {
            float4 a0 = *(const float4*)&xs[kk][ty * 8];
            float4 a1 = *(const float4*)&xs[kk][ty * 8 + 4];
            float4 b  = *(const float4*)&ws[kk][tx * 4];
            float av[8] = {a0.x, a0.y, a0.z, a0.w, a1.x, a1.y, a1.z, a1.w};
            float bv[4] = {b.x, b.y, b.z, b.w};
#pragma unroll
            for (int i = 0; i < 8; i++)
#pragma unroll
                for (int j = 0; j < 4; j++) acc[i][j] += av[i] * bv[j];
        }
        __syncthreads();
    }
#pragma unroll
    for (int i = 0; i < 8; i++) {
        int r = row0 + ty * 8 + i;
        if (r < M) {
            float4 v = make_float4(acc[i][0], acc[i][1], acc[i][2], acc[i][3]);
            *(float4*)&g_h1[(size_t)r * H1D + tx * 4] = v;
        }
    }
}

// ---------------- attention projections layer1 ----------------------------
__global__ void k_attn1(const float* __restrict__ att_s, const float* __restrict__ att_d, int N) {
    int t = blockIdx.x * blockDim.x + threadIdx.x;
    if (t >= N * HEADS) return;
    int n = t >> 3, h = t & 7;
    const float4* hp = (const float4*)g_h1 + (size_t)n * 16 + h * 2;
    float4 v0 = hp[0], v1 = hp[1];
    float4 s0 = __ldg((const float4*)att_s + h * 2);
    float4 s1 = __ldg((const float4*)att_s + h * 2 + 1);
    float4 d0 = __ldg((const float4*)att_d + h * 2);
    float4 d1 = __ldg((const float4*)att_d + h * 2 + 1);
    float as = v0.x * s0.x + v0.y * s0.y + v0.z * s0.z + v0.w * s0.w +
               v1.x * s1.x + v1.y * s1.y + v1.z * s1.z + v1.w * s1.w;
    float ad = v0.x * d0.x + v0.y * d0.y + v0.z * d0.z + v0.w * d0.w +
               v1.x * d1.x + v1.y * d1.y + v1.z * d1.z + v1.w * d1.w;
    g_as1[t] = as;
    g_ad1[t] = ad;
}

// ---------------- layer1 softmax denominators -----------------------------
__global__ void k_den1(int tot) {
    int e = blockIdx.x * blockDim.x + threadIdx.x;
    if (e >= tot) return;
    int s = g_src[e], d = g_dst[e];
    const float4* as = (const float4*)g_as1;
    const float4* ad = (const float4*)g_ad1;
    float4 a0 = as[s * 2], a1 = as[s * 2 + 1];
    float4 b0 = ad[d * 2], b1 = ad[d * 2 + 1];
    float4 p0, p1;
    p0.x = __expf(lrelu(a0.x + b0.x));
    p0.y = __expf(lrelu(a0.y + b0.y));
    p0.z = __expf(lrelu(a0.z + b0.z));
    p0.w = __expf(lrelu(a0.w + b0.w));
    p1.x = __expf(lrelu(a1.x + b1.x));
    p1.y = __expf(lrelu(a1.y + b1.y));
    p1.z = __expf(lrelu(a1.z + b1.z));
    p1.w = __expf(lrelu(a1.w + b1.w));
    atomicAdd((float4*)g_den1 + d * 2,     p0);
    atomicAdd((float4*)g_den1 + d * 2 + 1, p1);
}

// ---------------- layer1 weighted aggregation -----------------------------
__global__ void k_agg1(int tot) {
    int t = blockIdx.x * blockDim.x + threadIdx.x;
    if (t >= tot * 8) return;
    int e = t >> 3, h = t & 7;
    int s = g_src[e], d = g_dst[e];
    float ev = lrelu(g_as1[s * 8 + h] + g_ad1[d * 8 + h]);
    float alpha = __expf(ev) / g_den1[d * 8 + h];
    const float4* hp = (const float4*)g_h1;
    float4 v0 = hp[(size_t)s * 16 + h * 2];
    float4 v1 = hp[(size_t)s * 16 + h * 2 + 1];
    v0.x *= alpha; v0.y *= alpha; v0.z *= alpha; v0.w *= alpha;
    v1.x *= alpha; v1.y *= alpha; v1.z *= alpha; v1.w *= alpha;
    atomicAdd((float4*)g_acc1 + (size_t)d * 16 + h * 2,     v0);
    atomicAdd((float4*)g_acc1 + (size_t)d * 16 + h * 2 + 1, v1);
}

// ---------------- finalize1: +b1, elu, @W2, attention dots ----------------
__global__ __launch_bounds__(256) void k_fin1(const float* __restrict__ b1,
                                              const float* __restrict__ W2,
                                              const float* __restrict__ as2v,
                                              const float* __restrict__ ad2v, int N) {
    __shared__ float w2s[H1D * NCLS];
    __shared__ float b1s[H1D];
    __shared__ float s2[NCLS], d2[NCLS];
    int tid = threadIdx.x;
    for (int i = tid; i < H1D * NCLS; i += blockDim.x) w2s[i] = W2[i];
    if (tid < H1D) b1s[tid] = b1[tid];
    if (tid < NCLS) { s2[tid] = as2v[tid]; d2[tid] = ad2v[tid]; }
    __syncthreads();
    int n = blockIdx.x * blockDim.x + tid;
    if (n >= N) return;

    float h[H1D];
    const float4* ap = (const float4*)g_acc1 + (size_t)n * 16;
#pragma unroll
    for (int q = 0; q < 16; q++) {
        float4 v = ap[q];
        h[q * 4 + 0] = v.x; h[q * 4 + 1] = v.y; h[q * 4 + 2] = v.z; h[q * 4 + 3] = v.w;
    }
#pragma unroll
    for (int c = 0; c < H1D; c++) {
        float v = h[c] + b1s[c];
        h[c] = v > 0.0f ? v : expm1f(v);   // elu
    }
    float o[NCLS];
#pragma unroll
    for (int j = 0; j < NCLS; j++) o[j] = 0.0f;
#pragma unroll
    for (int c = 0; c < H1D; c++) {
        float hv = h[c];
#pragma unroll
        for (int j = 0; j < NCLS; j++) o[j] += hv * w2s[c * NCLS + j];
    }
    float4* h2p = (float4*)g_h2 + (size_t)n * 4;
#pragma unroll
    for (int q = 0; q < 4; q++)
        h2p[q] = make_float4(o[q * 4], o[q * 4 + 1], o[q * 4 + 2], o[q * 4 + 3]);
    float as = 0.0f, ad = 0.0f;
#pragma unroll
    for (int j = 0; j < NCLS; j++) { as += o[j] * s2[j]; ad += o[j] * d2[j]; }
    g_as2[n] = as;
    g_ad2[n] = ad;
}

// ---------------- layer2 denominators -------------------------------------
__global__ void k_den2(int tot) {
    int e = blockIdx.x * blockDim.x + threadIdx.x;
    if (e >= tot) return;
    int s = g_src[e], d = g_dst[e];
    float p = __expf(lrelu(g_as2[s] + g_ad2[d]));
    atomicAdd(&g_den2[d], p);
}

// ---------------- layer2 aggregation into output --------------------------
__global__ void k_agg2(float* __restrict__ out, int tot) {
    int t = blockIdx.x * blockDim.x + threadIdx.x;
    if (t >= tot * 4) return;
    int e = t >> 2, q = t & 3;
    int s = g_src[e], d = g_dst[e];
    float alpha = __expf(lrelu(g_as2[s] + g_ad2[d])) / g_den2[d];
    float4 v = ((const float4*)g_h2)[(size_t)s * 4 + q];
    v.x *= alpha; v.y *= alpha; v.z *= alpha; v.w *= alpha;
    atomicAdd((float4*)out + (size_t)d * 4 + q, v);
}

// ---------------- launch ---------------------------------------------------
extern "C" void kernel_launch(void* const* d_in, const int* in_sizes, int n_in,
                              void* d_out, int out_size) {
    const float* x    = (const float*)d_in[0];
    const int*   ei   = (const int*)d_in[1];   // int32 or int64 (detected)
    const float* W1   = (const float*)d_in[2];
    const float* as1v = (const float*)d_in[3];
    const float* ad1v = (const float*)d_in[4];
    const float* b1   = (const float*)d_in[5];
    const float* W2   = (const float*)d_in[6];
    const float* as2v = (const float*)d_in[7];
    const float* ad2v = (const float*)d_in[8];
    const float* b2   = (const float*)d_in[9];
    float* out = (float*)d_out;

    int E = in_sizes[1] / 2;
    int N = in_sizes[0] / FIN;
    int tot = E + N;

    k_detect<<<1, 256>>>(ei);
    k_edges<<<(tot + 255) / 256, 256>>>(ei, E, N);
    k_init<<<(N * H1D + 255) / 256, 256>>>(out, b2, N);
    k_gemm1<<<(N + GM_BM - 1) / GM_BM, 256>>>(x, W1, N);
    k_attn1<<<(N * HEADS + 255) / 256, 256>>>(as1v, ad1v, N);
    k_den1<<<(tot + 255) / 256, 256>>>(tot);
    k_agg1<<<(tot * 8 + 255) / 256, 256>>>(tot);
    k_fin1<<<(N + 255) / 256, 256>>>(b1, W2, as2v, ad2v, N);
    k_den2<<<(tot + 255) / 256, 256>>>(tot);
    k_agg2<<<(tot * 4 + 255) / 256, 256>>>(out, tot);
}